// round 7
// baseline (speedup 1.0000x reference)
#include <cuda_runtime.h>

#define NN 50000
#define NE 600000
#define HID 128
#define NG 64
#define NBLK 196   // ceil(50000/256)

// ---- device scratch (no allocations allowed) ----
__device__ int   g_cnt[3][NN];
__device__ float g_dinv[3][NN];
__device__ int   g_off[NN + 1];
__device__ int   g_cur[NN];
__device__ int   g_bsum[NBLK];
__device__ int   g_bpre[NBLK];
__device__ unsigned g_csr[NE];
__device__ __align__(16) float g_h[3][NN * HID];  // 0: gemm out, 1/2: activations
__device__ __align__(16) float g_pool[NG * HID];
__device__ float g_pcnt[NG];

// ---------------- init ----------------
__global__ void k_zero() {
    int i = blockIdx.x * blockDim.x + threadIdx.x;
    if (i < NN) { g_cnt[0][i] = 0; g_cnt[1][i] = 0; g_cnt[2][i] = 0; }
    if (i < NG * HID) g_pool[i] = 0.0f;
    if (i < NG) g_pcnt[i] = 0.0f;
}

// ---------------- degree histogram ----------------
__global__ void k_hist(const int* __restrict__ ei,
                       const int* __restrict__ em) {
    int e = blockIdx.x * blockDim.x + threadIdx.x;
    if (e >= NE) return;
    int d = ei[NE + e];
    int m = em[e];
    atomicAdd(&g_cnt[0][d], 1);
    if (m == 1) atomicAdd(&g_cnt[1][d], 1);
    else if (m == 2) atomicAdd(&g_cnt[2][d], 1);
}

// ---------------- scan pass A: per-block sums ----------------
__global__ void k_scanA() {
    int i = blockIdx.x * 256 + threadIdx.x;
    int lane = threadIdx.x & 31, warp = threadIdx.x >> 5;
    int v = (i < NN) ? g_cnt[0][i] : 0;
#pragma unroll
    for (int o = 16; o; o >>= 1) v += __shfl_xor_sync(0xFFFFFFFFu, v, o);
    __shared__ int ws[8];
    if (lane == 0) ws[warp] = v;
    __syncthreads();
    if (threadIdx.x == 0) {
        int s = 0;
#pragma unroll
        for (int j = 0; j < 8; j++) s += ws[j];
        g_bsum[blockIdx.x] = s;
    }
}

// ---------------- scan pass B: scan 196 block sums (1 block) ----------------
__global__ void k_scanB() {
    __shared__ int sh[256];
    int t = threadIdx.x;
    int v = (t < NBLK) ? g_bsum[t] : 0;
    sh[t] = v;
    __syncthreads();
    for (int d = 1; d < 256; d <<= 1) {
        int u = (t >= d) ? sh[t - d] : 0;
        __syncthreads();
        sh[t] += u;
        __syncthreads();
    }
    if (t < NBLK) g_bpre[t] = sh[t] - v;          // exclusive
    if (t == NBLK - 1) g_off[NN] = sh[t];         // total
}

// ---------------- scan pass C: local scan + apply prefix + dinv ----------------
__global__ void k_scanC() {
    int i = blockIdx.x * 256 + threadIdx.x;
    int lane = threadIdx.x & 31, warp = threadIdx.x >> 5;
    int v = (i < NN) ? g_cnt[0][i] : 0;
    int incl = v;
#pragma unroll
    for (int o = 1; o < 32; o <<= 1) {
        int t = __shfl_up_sync(0xFFFFFFFFu, incl, o);
        if (lane >= o) incl += t;
    }
    __shared__ int ws[8];
    if (lane == 31) ws[warp] = incl;
    __syncthreads();
    if (warp == 0 && lane < 8) {
        int s = ws[lane];
        int si = s;
#pragma unroll
        for (int o = 1; o < 8; o <<= 1) {
            int t = __shfl_up_sync(0xFFu, si, o);
            if (lane >= o) si += t;
        }
        ws[lane] = si - s;   // exclusive warp prefix
    }
    __syncthreads();
    if (i < NN) {
        int excl = (incl - v) + ws[warp] + g_bpre[blockIdx.x];
        g_off[i] = excl;
        g_cur[i] = excl;
        g_dinv[0][i] = rsqrtf((float)(v + 1));
        g_dinv[1][i] = rsqrtf((float)(g_cnt[1][i] + 1));
        g_dinv[2][i] = rsqrtf((float)(g_cnt[2][i] + 1));
    }
}

// ---------------- CSR scatter ----------------
__global__ void k_scatter(const int* __restrict__ ei,
                          const int* __restrict__ em) {
    int e = blockIdx.x * blockDim.x + threadIdx.x;
    if (e >= NE) return;
    int s = ei[e];
    int d = ei[NE + e];
    int m = em[e];
    int pos = atomicAdd(&g_cur[d], 1);
    g_csr[pos] = (unsigned)s | ((unsigned)m << 16);   // s < 50000 < 2^16
}

// ---------------- packed f32x2 FMA helpers ----------------
union F2 { float2 f; unsigned long long u; };
union WV { float4 f4; unsigned long long u[2]; };

#define FFMA2(d, a, b) \
    asm("fma.rn.f32x2 %0, %1, %2, %0;" : "+l"((d).u) : "l"((a).u), "l"((b).u))

// ---------------- GEMM: g_h[0] = IN @ W  (N x 128 @ 128 x 128) ----------------
// Outer-product SGEMM, 8x8 thread tile, FFMA2.
// X smem: row-major DUPLICATED [row][2k]=[row][2k+1]=a_k -> one LDS.128 gives
// two k-steps of dup'd multipliers, zero packing, coalesced GMEM load.
__global__ void __launch_bounds__(256, 3)
k_gemm(int inSel,              // -1: external X, else g_h[inSel]
       const float* __restrict__ Xext,
       const float* __restrict__ W) {
    __shared__ float Ws[32][HID];        // 16KB  [k][col]
    __shared__ float Xs2[128][64];       // 32KB  dup'd, stride 64 floats
    const float* X = (inSel < 0) ? Xext : g_h[inSel];

    int tid = threadIdx.x;
    int tx  = tid & 15;        // col group: cols tx*8..+8
    int ty  = tid >> 4;        // row group: rows ty*8..+8
    int rowBase = blockIdx.x * 128;

    F2 acc[8][4];
#pragma unroll
    for (int r = 0; r < 8; r++)
#pragma unroll
        for (int j = 0; j < 4; j++) acc[r][j].f = make_float2(0.f, 0.f);

    for (int kt = 0; kt < HID; kt += 32) {
        // W tile 32x128: 1024 float4, 4/thread, coalesced
#pragma unroll
        for (int i = 0; i < 4; i++) {
            int j = tid + i * 256;
            int kr = j >> 5, kc = (j & 31) * 4;
            *(float4*)&Ws[kr][kc] = *(const float4*)&W[(size_t)(kt + kr) * HID + kc];
        }
        // X tile 128 rows x 32 k: coalesced load (8 lanes cover one row),
        // duplicated store into row-major smem.
#pragma unroll
        for (int i = 0; i < 4; i++) {
            int j = tid + i * 256;            // 0..1023
            int row = j >> 3, kq = (j & 7) * 4;
            int grow = rowBase + row;
            float4 v = make_float4(0.f, 0.f, 0.f, 0.f);
            if (grow < NN) v = *(const float4*)&X[(size_t)grow * HID + kt + kq];
            *(float4*)&Xs2[row][2 * kq]     = make_float4(v.x, v.x, v.y, v.y);
            *(float4*)&Xs2[row][2 * kq + 4] = make_float4(v.z, v.z, v.w, v.w);
        }
        __syncthreads();

#pragma unroll 4
        for (int k2 = 0; k2 < 16; k2++) {       // two k per iteration
            WV b0, b1, c0, c1;
            b0.f4 = *(float4*)&Ws[2 * k2][tx * 8];
            b1.f4 = *(float4*)&Ws[2 * k2][tx * 8 + 4];
            c0.f4 = *(float4*)&Ws[2 * k2 + 1][tx * 8];
            c1.f4 = *(float4*)&Ws[2 * k2 + 1][tx * 8 + 4];
            F2 bk[4], ck[4];
            bk[0].u = b0.u[0]; bk[1].u = b0.u[1];
            bk[2].u = b1.u[0]; bk[3].u = b1.u[1];
            ck[0].u = c0.u[0]; ck[1].u = c0.u[1];
            ck[2].u = c1.u[0]; ck[3].u = c1.u[1];
#pragma unroll
            for (int r = 0; r < 8; r++) {
                WV av;
                av.f4 = *(float4*)&Xs2[ty * 8 + r][4 * k2]; // (ak,ak,ak1,ak1)
                F2 a0, a1;
                a0.u = av.u[0]; a1.u = av.u[1];
#pragma unroll
                for (int j = 0; j < 4; j++) FFMA2(acc[r][j], a0, bk[j]);
#pragma unroll
                for (int j = 0; j < 4; j++) FFMA2(acc[r][j], a1, ck[j]);
            }
        }
        __syncthreads();
    }

#pragma unroll
    for (int r = 0; r < 8; r++) {
        int row = rowBase + ty * 8 + r;
        if (row < NN) {
            float4 o0, o1;
            o0.x = acc[r][0].f.x; o0.y = acc[r][0].f.y;
            o0.z = acc[r][1].f.x; o0.w = acc[r][1].f.y;
            o1.x = acc[r][2].f.x; o1.y = acc[r][2].f.y;
            o1.z = acc[r][3].f.x; o1.w = acc[r][3].f.y;
            *(float4*)&g_h[0][(size_t)row * HID + tx * 8]     = o0;
            *(float4*)&g_h[0][(size_t)row * HID + tx * 8 + 4] = o1;
        }
    }
}

// ---------------- aggregation: warp per node ----------------
__global__ void k_agg(int layer, int outSel,
                      const float* __restrict__ bias,
                      int mode, int do_relu,
                      int doPool, const int* __restrict__ batch) {
    int wi = (blockIdx.x * blockDim.x + threadIdx.x) >> 5;
    if (wi >= NN) return;
    int lane = threadIdx.x & 31;

    const float* dinv = g_dinv[layer];
    float di = dinv[wi];
    int e0 = g_off[wi], e1 = g_off[wi + 1];

    float ax = 0.f, ay = 0.f, az = 0.f, aw = 0.f;
    for (int e = e0; e < e1; e++) {
        unsigned p = g_csr[e];
        int m = (int)(p >> 16);
        if (mode == 0 || m == mode) {
            int s = (int)(p & 0xFFFFu);
            float c = di * dinv[s];
            float4 hv = *(const float4*)&g_h[0][(size_t)s * HID + lane * 4];
            ax += c * hv.x; ay += c * hv.y; az += c * hv.z; aw += c * hv.w;
        }
    }
    float4 hs = *(const float4*)&g_h[0][(size_t)wi * HID + lane * 4];
    float c2 = di * di;
    ax += c2 * hs.x; ay += c2 * hs.y; az += c2 * hs.z; aw += c2 * hs.w;

    float4 bv = *(const float4*)&bias[lane * 4];
    ax += bv.x; ay += bv.y; az += bv.z; aw += bv.w;

    if (do_relu) {
        ax = fmaxf(ax, 0.f); ay = fmaxf(ay, 0.f);
        az = fmaxf(az, 0.f); aw = fmaxf(aw, 0.f);
    }
    float4 o; o.x = ax; o.y = ay; o.z = az; o.w = aw;
    *(float4*)&g_h[outSel][(size_t)wi * HID + lane * 4] = o;

    if (doPool) {
        int g = batch[wi];
        float* base = &g_pool[g * HID + lane * 4];
        atomicAdd(base + 0, ax);
        atomicAdd(base + 1, ay);
        atomicAdd(base + 2, az);
        atomicAdd(base + 3, aw);
        if (lane == 0) atomicAdd(&g_pcnt[g], 1.0f);
    }
}

// ---------------- head ----------------
__global__ void k_final(const float* __restrict__ Wl,
                        const float* __restrict__ bl,
                        float* __restrict__ out) {
    int g = blockIdx.x;
    int lane = threadIdx.x;
    float inv = 1.0f / fmaxf(g_pcnt[g], 1.0f);
    float s = 0.f;
    for (int j = lane; j < HID; j += 32)
        s += g_pool[g * HID + j] * inv * Wl[j];
#pragma unroll
    for (int o = 16; o; o >>= 1) s += __shfl_xor_sync(0xFFFFFFFFu, s, o);
    if (lane == 0) out[g] = s + bl[0];
}

// ---------------- launcher: kernel launches ONLY ----------------
extern "C" void kernel_launch(void* const* d_in, const int* in_sizes, int n_in,
                              void* d_out, int out_size) {
    const float* x     = (const float*)d_in[0];
    const int*   ei    = (const int*)d_in[1];    // int32 (JAX x64 disabled)
    const int*   em    = (const int*)d_in[2];
    const int*   batch = (const int*)d_in[3];
    const float* W1 = (const float*)d_in[4];
    const float* b1 = (const float*)d_in[5];
    const float* W2 = (const float*)d_in[6];
    const float* b2 = (const float*)d_in[7];
    const float* W3 = (const float*)d_in[8];
    const float* b3 = (const float*)d_in[9];
    const float* Wl = (const float*)d_in[10];
    const float* bl = (const float*)d_in[11];
    float* out = (float*)d_out;

    const int tb  = 256;
    const int gbN = (NN + tb - 1) / tb;
    const int gbE = (NE + tb - 1) / tb;
    const int gbW = (NN * 32 + tb - 1) / tb;   // warp-per-node
    const int gbG = (NN + 127) / 128;          // gemm: 128 rows/block

    k_zero   <<<gbN, tb>>>();
    k_hist   <<<gbE, tb>>>(ei, em);
    k_scanA  <<<NBLK, 256>>>();
    // GEMM1 independent of CSR build — stays at launch #4 for ncu
    k_gemm   <<<gbG, tb>>>(-1, x, W1);
    k_scanB  <<<1, 256>>>();
    k_scanC  <<<NBLK, 256>>>();                // + fused dinv
    k_scatter<<<gbE, tb>>>(ei, em);

    // layer 1: g_h[0] -> g_h[1] (relu, all edges)
    k_agg <<<gbW, tb>>>(0, 1, b1, 0, 1, 0, batch);
    // layer 2: g_h[1] -> g_h[0] -> g_h[2] (relu, mask==1)
    k_gemm<<<gbG, tb>>>(1, x, W2);
    k_agg <<<gbW, tb>>>(1, 2, b2, 1, 1, 0, batch);
    // layer 3: g_h[2] -> g_h[0] -> g_h[1] (no relu, mask==2) + fused pool
    k_gemm<<<gbG, tb>>>(2, x, W3);
    k_agg <<<gbW, tb>>>(2, 1, b3, 2, 0, 1, batch);

    k_final<<<NG, 32>>>(Wl, bl, out);
}

// round 8
// speedup vs baseline: 1.0955x; 1.0955x over previous
#include <cuda_runtime.h>

#define NN 50000
#define NE 600000
#define HID 128
#define NG 64
#define NBLK 196   // ceil(50000/256)

// ---- device scratch (no allocations allowed) ----
__device__ int   g_cnt[3][NN];
__device__ float g_dinv[3][NN];
__device__ int   g_off[NN + 1];
__device__ int   g_cur[NN];
__device__ int   g_bsum[NBLK];
__device__ int   g_bpre[NBLK];
__device__ unsigned g_csr[NE];
__device__ __align__(16) float g_h[3][NN * HID];  // 0: gemm out, 1/2: activations
__device__ __align__(16) float g_pool[NG * HID];
__device__ float g_pcnt[NG];

// ---------------- init ----------------
__global__ void k_zero() {
    int i = blockIdx.x * blockDim.x + threadIdx.x;
    if (i < NN) { g_cnt[0][i] = 0; g_cnt[1][i] = 0; g_cnt[2][i] = 0; }
    if (i < NG * HID) g_pool[i] = 0.0f;
    if (i < NG) g_pcnt[i] = 0.0f;
}

// ---------------- degree histogram ----------------
__global__ void k_hist(const int* __restrict__ ei,
                       const int* __restrict__ em) {
    int e = blockIdx.x * blockDim.x + threadIdx.x;
    if (e >= NE) return;
    int d = ei[NE + e];
    int m = em[e];
    atomicAdd(&g_cnt[0][d], 1);
    if (m == 1) atomicAdd(&g_cnt[1][d], 1);
    else if (m == 2) atomicAdd(&g_cnt[2][d], 1);
}

// ---------------- scan pass A: per-block sums ----------------
__global__ void k_scanA() {
    int i = blockIdx.x * 256 + threadIdx.x;
    int lane = threadIdx.x & 31, warp = threadIdx.x >> 5;
    int v = (i < NN) ? g_cnt[0][i] : 0;
#pragma unroll
    for (int o = 16; o; o >>= 1) v += __shfl_xor_sync(0xFFFFFFFFu, v, o);
    __shared__ int ws[8];
    if (lane == 0) ws[warp] = v;
    __syncthreads();
    if (threadIdx.x == 0) {
        int s = 0;
#pragma unroll
        for (int j = 0; j < 8; j++) s += ws[j];
        g_bsum[blockIdx.x] = s;
    }
}

// ---------------- scan pass B: scan 196 block sums (1 block) ----------------
__global__ void k_scanB() {
    __shared__ int sh[256];
    int t = threadIdx.x;
    int v = (t < NBLK) ? g_bsum[t] : 0;
    sh[t] = v;
    __syncthreads();
    for (int d = 1; d < 256; d <<= 1) {
        int u = (t >= d) ? sh[t - d] : 0;
        __syncthreads();
        sh[t] += u;
        __syncthreads();
    }
    if (t < NBLK) g_bpre[t] = sh[t] - v;          // exclusive
    if (t == NBLK - 1) g_off[NN] = sh[t];         // total
}

// ---------------- scan pass C: local scan + apply prefix + dinv ----------------
__global__ void k_scanC() {
    int i = blockIdx.x * 256 + threadIdx.x;
    int lane = threadIdx.x & 31, warp = threadIdx.x >> 5;
    int v = (i < NN) ? g_cnt[0][i] : 0;
    int incl = v;
#pragma unroll
    for (int o = 1; o < 32; o <<= 1) {
        int t = __shfl_up_sync(0xFFFFFFFFu, incl, o);
        if (lane >= o) incl += t;
    }
    __shared__ int ws[8];
    if (lane == 31) ws[warp] = incl;
    __syncthreads();
    if (warp == 0 && lane < 8) {
        int s = ws[lane];
        int si = s;
#pragma unroll
        for (int o = 1; o < 8; o <<= 1) {
            int t = __shfl_up_sync(0xFFu, si, o);
            if (lane >= o) si += t;
        }
        ws[lane] = si - s;   // exclusive warp prefix
    }
    __syncthreads();
    if (i < NN) {
        int excl = (incl - v) + ws[warp] + g_bpre[blockIdx.x];
        g_off[i] = excl;
        g_cur[i] = excl;
        g_dinv[0][i] = rsqrtf((float)(v + 1));
        g_dinv[1][i] = rsqrtf((float)(g_cnt[1][i] + 1));
        g_dinv[2][i] = rsqrtf((float)(g_cnt[2][i] + 1));
    }
}

// ---------------- CSR scatter ----------------
__global__ void k_scatter(const int* __restrict__ ei,
                          const int* __restrict__ em) {
    int e = blockIdx.x * blockDim.x + threadIdx.x;
    if (e >= NE) return;
    int s = ei[e];
    int d = ei[NE + e];
    int m = em[e];
    int pos = atomicAdd(&g_cur[d], 1);
    g_csr[pos] = (unsigned)s | ((unsigned)m << 16);   // s < 50000 < 2^16
}

// ---------------- packed f32x2 FMA helpers ----------------
union F2 { float2 f; unsigned long long u; };
union WV { float4 f4; unsigned long long u[2]; };

#define FFMA2(d, a, b) \
    asm("fma.rn.f32x2 %0, %1, %2, %0;" : "+l"((d).u) : "l"((a).u), "l"((b).u))

// ---------------- GEMM: g_h[0] = IN @ W  (N x 128 @ 128 x 128) ----------------
// Outer-product SGEMM, thread tile 4 rows x 8 cols (16 F2 accs = 32 regs,
// NO SPILL under 84-reg cap). Block tile 64x128, 256 threads, K-tile 32.
// X dup'd row-major: one LDS.128 = (ak,ak,ak+1,ak+1). 40 slots / 64 FMA.
__global__ void __launch_bounds__(256, 3)
k_gemm(int inSel,              // -1: external X, else g_h[inSel]
       const float* __restrict__ Xext,
       const float* __restrict__ W) {
    __shared__ float Ws[32][HID];        // 16KB  [k][col]
    __shared__ float Xs2[64][64];        // 16KB  dup'd [row][2k]=[row][2k+1]=a_k
    const float* X = (inSel < 0) ? Xext : g_h[inSel];

    int tid = threadIdx.x;
    int tx  = tid & 15;        // col group: cols tx*8..+8
    int ty  = tid >> 4;        // row group: rows ty*4..+4
    int rowBase = blockIdx.x * 64;

    F2 acc[4][4];
#pragma unroll
    for (int r = 0; r < 4; r++)
#pragma unroll
        for (int j = 0; j < 4; j++) acc[r][j].f = make_float2(0.f, 0.f);

    for (int kt = 0; kt < HID; kt += 32) {
        // W tile 32x128: 1024 float4, 4/thread, coalesced
#pragma unroll
        for (int i = 0; i < 4; i++) {
            int j = tid + i * 256;
            int kr = j >> 5, kc = (j & 31) * 4;
            *(float4*)&Ws[kr][kc] = *(const float4*)&W[(size_t)(kt + kr) * HID + kc];
        }
        // X tile 64 rows x 32 k: 512 source float4, 2/thread; dup'd store
#pragma unroll
        for (int i = 0; i < 2; i++) {
            int j = tid + i * 256;            // 0..511
            int row = j >> 3, kq = (j & 7) * 4;
            int grow = rowBase + row;
            float4 v = make_float4(0.f, 0.f, 0.f, 0.f);
            if (grow < NN) v = *(const float4*)&X[(size_t)grow * HID + kt + kq];
            *(float4*)&Xs2[row][2 * kq]     = make_float4(v.x, v.x, v.y, v.y);
            *(float4*)&Xs2[row][2 * kq + 4] = make_float4(v.z, v.z, v.w, v.w);
        }
        __syncthreads();

#pragma unroll 4
        for (int k2 = 0; k2 < 16; k2++) {       // two k per iteration
            WV b0, b1, c0, c1;
            b0.f4 = *(float4*)&Ws[2 * k2][tx * 8];
            b1.f4 = *(float4*)&Ws[2 * k2][tx * 8 + 4];
            c0.f4 = *(float4*)&Ws[2 * k2 + 1][tx * 8];
            c1.f4 = *(float4*)&Ws[2 * k2 + 1][tx * 8 + 4];
            F2 bk[4], ck[4];
            bk[0].u = b0.u[0]; bk[1].u = b0.u[1];
            bk[2].u = b1.u[0]; bk[3].u = b1.u[1];
            ck[0].u = c0.u[0]; ck[1].u = c0.u[1];
            ck[2].u = c1.u[0]; ck[3].u = c1.u[1];
#pragma unroll
            for (int r = 0; r < 4; r++) {
                WV av;
                av.f4 = *(float4*)&Xs2[ty * 4 + r][4 * k2]; // (ak,ak,ak1,ak1)
                F2 a0, a1;
                a0.u = av.u[0]; a1.u = av.u[1];
#pragma unroll
                for (int j = 0; j < 4; j++) FFMA2(acc[r][j], a0, bk[j]);
#pragma unroll
                for (int j = 0; j < 4; j++) FFMA2(acc[r][j], a1, ck[j]);
            }
        }
        __syncthreads();
    }

#pragma unroll
    for (int r = 0; r < 4; r++) {
        int row = rowBase + ty * 4 + r;
        if (row < NN) {
            float4 o0, o1;
            o0.x = acc[r][0].f.x; o0.y = acc[r][0].f.y;
            o0.z = acc[r][1].f.x; o0.w = acc[r][1].f.y;
            o1.x = acc[r][2].f.x; o1.y = acc[r][2].f.y;
            o1.z = acc[r][3].f.x; o1.w = acc[r][3].f.y;
            *(float4*)&g_h[0][(size_t)row * HID + tx * 8]     = o0;
            *(float4*)&g_h[0][(size_t)row * HID + tx * 8 + 4] = o1;
        }
    }
}

// ---------------- aggregation: warp per node ----------------
__global__ void k_agg(int layer, int outSel,
                      const float* __restrict__ bias,
                      int mode, int do_relu,
                      int doPool, const int* __restrict__ batch) {
    int wi = (blockIdx.x * blockDim.x + threadIdx.x) >> 5;
    if (wi >= NN) return;
    int lane = threadIdx.x & 31;

    const float* dinv = g_dinv[layer];
    float di = dinv[wi];
    int e0 = g_off[wi], e1 = g_off[wi + 1];

    float ax = 0.f, ay = 0.f, az = 0.f, aw = 0.f;
    for (int e = e0; e < e1; e++) {
        unsigned p = g_csr[e];
        int m = (int)(p >> 16);
        if (mode == 0 || m == mode) {
            int s = (int)(p & 0xFFFFu);
            float c = di * dinv[s];
            float4 hv = *(const float4*)&g_h[0][(size_t)s * HID + lane * 4];
            ax += c * hv.x; ay += c * hv.y; az += c * hv.z; aw += c * hv.w;
        }
    }
    float4 hs = *(const float4*)&g_h[0][(size_t)wi * HID + lane * 4];
    float c2 = di * di;
    ax += c2 * hs.x; ay += c2 * hs.y; az += c2 * hs.z; aw += c2 * hs.w;

    float4 bv = *(const float4*)&bias[lane * 4];
    ax += bv.x; ay += bv.y; az += bv.z; aw += bv.w;

    if (do_relu) {
        ax = fmaxf(ax, 0.f); ay = fmaxf(ay, 0.f);
        az = fmaxf(az, 0.f); aw = fmaxf(aw, 0.f);
    }
    float4 o; o.x = ax; o.y = ay; o.z = az; o.w = aw;
    *(float4*)&g_h[outSel][(size_t)wi * HID + lane * 4] = o;

    if (doPool) {
        int g = batch[wi];
        float* base = &g_pool[g * HID + lane * 4];
        atomicAdd(base + 0, ax);
        atomicAdd(base + 1, ay);
        atomicAdd(base + 2, az);
        atomicAdd(base + 3, aw);
        if (lane == 0) atomicAdd(&g_pcnt[g], 1.0f);
    }
}

// ---------------- head ----------------
__global__ void k_final(const float* __restrict__ Wl,
                        const float* __restrict__ bl,
                        float* __restrict__ out) {
    int g = blockIdx.x;
    int lane = threadIdx.x;
    float inv = 1.0f / fmaxf(g_pcnt[g], 1.0f);
    float s = 0.f;
    for (int j = lane; j < HID; j += 32)
        s += g_pool[g * HID + j] * inv * Wl[j];
#pragma unroll
    for (int o = 16; o; o >>= 1) s += __shfl_xor_sync(0xFFFFFFFFu, s, o);
    if (lane == 0) out[g] = s + bl[0];
}

// ---------------- launcher: kernel launches ONLY ----------------
extern "C" void kernel_launch(void* const* d_in, const int* in_sizes, int n_in,
                              void* d_out, int out_size) {
    const float* x     = (const float*)d_in[0];
    const int*   ei    = (const int*)d_in[1];    // int32 (JAX x64 disabled)
    const int*   em    = (const int*)d_in[2];
    const int*   batch = (const int*)d_in[3];
    const float* W1 = (const float*)d_in[4];
    const float* b1 = (const float*)d_in[5];
    const float* W2 = (const float*)d_in[6];
    const float* b2 = (const float*)d_in[7];
    const float* W3 = (const float*)d_in[8];
    const float* b3 = (const float*)d_in[9];
    const float* Wl = (const float*)d_in[10];
    const float* bl = (const float*)d_in[11];
    float* out = (float*)d_out;

    const int tb  = 256;
    const int gbN = (NN + tb - 1) / tb;
    const int gbE = (NE + tb - 1) / tb;
    const int gbW = (NN * 32 + tb - 1) / tb;   // warp-per-node
    const int gbG = (NN + 63) / 64;            // gemm: 64 rows/block

    k_zero   <<<gbN, tb>>>();
    k_hist   <<<gbE, tb>>>(ei, em);
    k_scanA  <<<NBLK, 256>>>();
    // GEMM1 independent of CSR build — stays at launch #4 for ncu
    k_gemm   <<<gbG, tb>>>(-1, x, W1);
    k_scanB  <<<1, 256>>>();
    k_scanC  <<<NBLK, 256>>>();                // + fused dinv
    k_scatter<<<gbE, tb>>>(ei, em);

    // layer 1: g_h[0] -> g_h[1] (relu, all edges)
    k_agg <<<gbW, tb>>>(0, 1, b1, 0, 1, 0, batch);
    // layer 2: g_h[1] -> g_h[0] -> g_h[2] (relu, mask==1)
    k_gemm<<<gbG, tb>>>(1, x, W2);
    k_agg <<<gbW, tb>>>(1, 2, b2, 1, 1, 0, batch);
    // layer 3: g_h[2] -> g_h[0] -> g_h[1] (no relu, mask==2) + fused pool
    k_gemm<<<gbG, tb>>>(2, x, W3);
    k_agg <<<gbW, tb>>>(2, 1, b3, 2, 0, 1, batch);

    k_final<<<NG, 32>>>(Wl, bl, out);
}

// round 12
// speedup vs baseline: 1.4119x; 1.2888x over previous
#include <cuda_runtime.h>

#define NN 50000
#define NE 600000
#define HID 128
#define NG 64
#define NBLK 196        // ceil(50000/256)
#define GEMM_CTAS 782   // ceil(50000/64)

// ---- device scratch (no allocations allowed) ----
__device__ int   g_cnt[3][NN];
__device__ float g_dinv[3][NN];
__device__ int   g_off[NN + 1];
__device__ int   g_cur[NN];
__device__ int   g_bsum[NBLK];
__device__ int   g_bpre[NBLK];
__device__ unsigned g_csr[NE];
__device__ __align__(16) float g_h[3][NN * HID];
__device__ __align__(16) float g_pool[NG * HID];
__device__ float g_pcnt[NG];
// tf32 hi/lo bit-pattern images of W, row-major [k][n]
__device__ __align__(16) unsigned g_Wh32[3][HID * HID];
__device__ __align__(16) unsigned g_Wl32[3][HID * HID];

__device__ __forceinline__ unsigned to_tf32(float v) {
    unsigned u;
    asm("cvt.rna.tf32.f32 %0, %1;" : "=r"(u) : "f"(v));
    return u;
}

// ---------------- init ----------------
__global__ void k_zero() {
    int i = blockIdx.x * blockDim.x + threadIdx.x;
    if (i < NN) { g_cnt[0][i] = 0; g_cnt[1][i] = 0; g_cnt[2][i] = 0; }
    if (i < NG * HID) g_pool[i] = 0.0f;
    if (i < NG) g_pcnt[i] = 0.0f;
}

// ---------------- W prep: f32 -> tf32 hi/lo bit images ----------------
__global__ void k_prepW(const float* __restrict__ W1,
                        const float* __restrict__ W2,
                        const float* __restrict__ W3) {
    int sel = blockIdx.x >> 6;
    int idx = (blockIdx.x & 63) * 256 + threadIdx.x;   // 0..16383
    const float* W = sel == 0 ? W1 : (sel == 1 ? W2 : W3);
    float v = W[idx];
    unsigned uh = to_tf32(v);
    float lo = v - __uint_as_float(uh);
    g_Wh32[sel][idx] = uh;
    g_Wl32[sel][idx] = to_tf32(lo);
}

// ---------------- degree histogram ----------------
__global__ void k_hist(const int* __restrict__ ei,
                       const int* __restrict__ em) {
    int e = blockIdx.x * blockDim.x + threadIdx.x;
    if (e >= NE) return;
    int d = ei[NE + e];
    int m = em[e];
    atomicAdd(&g_cnt[0][d], 1);
    if (m == 1) atomicAdd(&g_cnt[1][d], 1);
    else if (m == 2) atomicAdd(&g_cnt[2][d], 1);
}

// ---------------- scan passes ----------------
__global__ void k_scanA() {
    int i = blockIdx.x * 256 + threadIdx.x;
    int lane = threadIdx.x & 31, warp = threadIdx.x >> 5;
    int v = (i < NN) ? g_cnt[0][i] : 0;
#pragma unroll
    for (int o = 16; o; o >>= 1) v += __shfl_xor_sync(0xFFFFFFFFu, v, o);
    __shared__ int ws[8];
    if (lane == 0) ws[warp] = v;
    __syncthreads();
    if (threadIdx.x == 0) {
        int s = 0;
#pragma unroll
        for (int j = 0; j < 8; j++) s += ws[j];
        g_bsum[blockIdx.x] = s;
    }
}

__global__ void k_scanB() {
    __shared__ int sh[256];
    int t = threadIdx.x;
    int v = (t < NBLK) ? g_bsum[t] : 0;
    sh[t] = v;
    __syncthreads();
    for (int d = 1; d < 256; d <<= 1) {
        int u = (t >= d) ? sh[t - d] : 0;
        __syncthreads();
        sh[t] += u;
        __syncthreads();
    }
    if (t < NBLK) g_bpre[t] = sh[t] - v;
    if (t == NBLK - 1) g_off[NN] = sh[t];
}

__global__ void k_scanC() {
    int i = blockIdx.x * 256 + threadIdx.x;
    int lane = threadIdx.x & 31, warp = threadIdx.x >> 5;
    int v = (i < NN) ? g_cnt[0][i] : 0;
    int incl = v;
#pragma unroll
    for (int o = 1; o < 32; o <<= 1) {
        int t = __shfl_up_sync(0xFFFFFFFFu, incl, o);
        if (lane >= o) incl += t;
    }
    __shared__ int ws[8];
    if (lane == 31) ws[warp] = incl;
    __syncthreads();
    if (warp == 0 && lane < 8) {
        int s = ws[lane];
        int si = s;
#pragma unroll
        for (int o = 1; o < 8; o <<= 1) {
            int t = __shfl_up_sync(0xFFu, si, o);
            if (lane >= o) si += t;
        }
        ws[lane] = si - s;
    }
    __syncthreads();
    if (i < NN) {
        int excl = (incl - v) + ws[warp] + g_bpre[blockIdx.x];
        g_off[i] = excl;
        g_cur[i] = excl;
        g_dinv[0][i] = rsqrtf((float)(v + 1));
        g_dinv[1][i] = rsqrtf((float)(g_cnt[1][i] + 1));
        g_dinv[2][i] = rsqrtf((float)(g_cnt[2][i] + 1));
    }
}

// ---------------- CSR scatter ----------------
__global__ void k_scatter(const int* __restrict__ ei,
                          const int* __restrict__ em) {
    int e = blockIdx.x * blockDim.x + threadIdx.x;
    if (e >= NE) return;
    int s = ei[e];
    int d = ei[NE + e];
    int m = em[e];
    int pos = atomicAdd(&g_cur[d], 1);
    g_csr[pos] = (unsigned)s | ((unsigned)m << 16);
}

// ---------------- tensor-core GEMM via mma.sync tf32 (split hi/lo) ----------
// block 64x128, 8 warps (2 row x 4 col), warp tile 32x32, K-tile 16.
// W images selected DEVICE-SIDE by wsel (never pass __device__ addrs from host).
#define MMA_TF32(d, a, b)                                                     \
    asm volatile("mma.sync.aligned.m16n8k8.row.col.f32.tf32.tf32.f32 "        \
        "{%0,%1,%2,%3}, {%4,%5,%6,%7}, {%8,%9}, {%0,%1,%2,%3};"               \
        : "+f"((d)[0]), "+f"((d)[1]), "+f"((d)[2]), "+f"((d)[3])              \
        : "r"((a)[0]), "r"((a)[1]), "r"((a)[2]), "r"((a)[3]),                 \
          "r"((b)[0]), "r"((b)[1]))

__global__ void __launch_bounds__(256, 1)
k_gemm_mma(int inSel, const float* __restrict__ Xext, int wsel) {
    __shared__ unsigned Xh[64][20], Xl[64][20];       // X tile hi/lo, K-tile 16
    __shared__ unsigned Whs[16][136], Wls[16][136];   // W tile hi/lo (pad 136)
    const float* X = (inSel < 0) ? Xext : g_h[inSel];
    const unsigned* __restrict__ Wh = g_Wh32[wsel];
    const unsigned* __restrict__ Wl = g_Wl32[wsel];

    int tid  = threadIdx.x;
    int lane = tid & 31;
    int wid  = tid >> 5;
    int wRow = (wid & 1) * 32;          // warp row offset in block tile
    int wCol = (wid >> 1) * 32;         // warp col offset
    int rowBase = blockIdx.x * 64;

    int lr = lane >> 2;                 // 0..7
    int lc = lane & 3;                  // 0..3

    float acc[2][4][4];                 // [tr][tc][frag]
#pragma unroll
    for (int a = 0; a < 2; a++)
#pragma unroll
        for (int b = 0; b < 4; b++)
#pragma unroll
            for (int c = 0; c < 4; c++) acc[a][b][c] = 0.f;

    for (int kt = 0; kt < HID; kt += 16) {
        // X tile: 64 rows x 16 k = 256 float4, 1/thread; split hi/lo
        {
            int row = tid >> 2, kq = (tid & 3) * 4;
            int grow = rowBase + row;
            float4 v = make_float4(0.f, 0.f, 0.f, 0.f);
            if (grow < NN) v = *(const float4*)&X[(size_t)grow * HID + kt + kq];
            unsigned h0 = to_tf32(v.x), h1 = to_tf32(v.y),
                     h2 = to_tf32(v.z), h3 = to_tf32(v.w);
            uint4 hv = make_uint4(h0, h1, h2, h3);
            uint4 lv = make_uint4(to_tf32(v.x - __uint_as_float(h0)),
                                  to_tf32(v.y - __uint_as_float(h1)),
                                  to_tf32(v.z - __uint_as_float(h2)),
                                  to_tf32(v.w - __uint_as_float(h3)));
            *(uint4*)&Xh[row][kq] = hv;
            *(uint4*)&Xl[row][kq] = lv;
        }
        // W tile: 16 k x 128 n = 512 uint4, 2/thread (hi and lo)
#pragma unroll
        for (int i = 0; i < 2; i++) {
            int j = tid + i * 256;                 // 0..511
            int kr = j >> 5, n0 = (j & 31) * 4;
            *(uint4*)&Whs[kr][n0] = *(const uint4*)&Wh[(kt + kr) * HID + n0];
            *(uint4*)&Wls[kr][n0] = *(const uint4*)&Wl[(kt + kr) * HID + n0];
        }
        __syncthreads();

#pragma unroll
        for (int ks = 0; ks < 16; ks += 8) {
            unsigned bh[4][2], bl[4][2];
#pragma unroll
            for (int tc = 0; tc < 4; tc++) {
                int n = wCol + tc * 8 + lr;
                bh[tc][0] = Whs[ks + lc][n];
                bh[tc][1] = Whs[ks + lc + 4][n];
                bl[tc][0] = Wls[ks + lc][n];
                bl[tc][1] = Wls[ks + lc + 4][n];
            }
#pragma unroll
            for (int tr = 0; tr < 2; tr++) {
                int r = wRow + tr * 16 + lr;
                unsigned ah[4], al[4];
                ah[0] = Xh[r][ks + lc];       ah[1] = Xh[r + 8][ks + lc];
                ah[2] = Xh[r][ks + lc + 4];   ah[3] = Xh[r + 8][ks + lc + 4];
                al[0] = Xl[r][ks + lc];       al[1] = Xl[r + 8][ks + lc];
                al[2] = Xl[r][ks + lc + 4];   al[3] = Xl[r + 8][ks + lc + 4];
#pragma unroll
                for (int tc = 0; tc < 4; tc++) {
                    MMA_TF32(acc[tr][tc], ah, bh[tc]);
                    MMA_TF32(acc[tr][tc], al, bh[tc]);
                    MMA_TF32(acc[tr][tc], ah, bl[tc]);
                }
            }
        }
        __syncthreads();
    }

    // epilogue: c0,c1 at (row, 2lc), c2,c3 at (row+8, 2lc)
#pragma unroll
    for (int tr = 0; tr < 2; tr++) {
        int r0 = rowBase + wRow + tr * 16 + lr;
#pragma unroll
        for (int tc = 0; tc < 4; tc++) {
            int col = wCol + tc * 8 + 2 * lc;
            if (r0 < NN)
                *(float2*)&g_h[0][(size_t)r0 * HID + col] =
                    make_float2(acc[tr][tc][0], acc[tr][tc][1]);
            if (r0 + 8 < NN)
                *(float2*)&g_h[0][(size_t)(r0 + 8) * HID + col] =
                    make_float2(acc[tr][tc][2], acc[tr][tc][3]);
        }
    }
}

// ---------------- aggregation: warp per node ----------------
__global__ void k_agg(int layer, int outSel,
                      const float* __restrict__ bias,
                      int mode, int do_relu,
                      int doPool, const int* __restrict__ batch) {
    int wi = (blockIdx.x * blockDim.x + threadIdx.x) >> 5;
    if (wi >= NN) return;
    int lane = threadIdx.x & 31;

    const float* dinv = g_dinv[layer];
    float di = dinv[wi];
    int e0 = g_off[wi], e1 = g_off[wi + 1];

    float ax = 0.f, ay = 0.f, az = 0.f, aw = 0.f;
    for (int e = e0; e < e1; e++) {
        unsigned p = g_csr[e];
        int m = (int)(p >> 16);
        if (mode == 0 || m == mode) {
            int s = (int)(p & 0xFFFFu);
            float c = di * dinv[s];
            float4 hv = *(const float4*)&g_h[0][(size_t)s * HID + lane * 4];
            ax += c * hv.x; ay += c * hv.y; az += c * hv.z; aw += c * hv.w;
        }
    }
    float4 hs = *(const float4*)&g_h[0][(size_t)wi * HID + lane * 4];
    float c2 = di * di;
    ax += c2 * hs.x; ay += c2 * hs.y; az += c2 * hs.z; aw += c2 * hs.w;

    float4 bv = *(const float4*)&bias[lane * 4];
    ax += bv.x; ay += bv.y; az += bv.z; aw += bv.w;

    if (do_relu) {
        ax = fmaxf(ax, 0.f); ay = fmaxf(ay, 0.f);
        az = fmaxf(az, 0.f); aw = fmaxf(aw, 0.f);
    }
    float4 o; o.x = ax; o.y = ay; o.z = az; o.w = aw;
    *(float4*)&g_h[outSel][(size_t)wi * HID + lane * 4] = o;

    if (doPool) {
        int g = batch[wi];
        float* base = &g_pool[g * HID + lane * 4];
        atomicAdd(base + 0, ax);
        atomicAdd(base + 1, ay);
        atomicAdd(base + 2, az);
        atomicAdd(base + 3, aw);
        if (lane == 0) atomicAdd(&g_pcnt[g], 1.0f);
    }
}

// ---------------- head ----------------
__global__ void k_final(const float* __restrict__ Wl,
                        const float* __restrict__ bl,
                        float* __restrict__ out) {
    int g = blockIdx.x;
    int lane = threadIdx.x;
    float inv = 1.0f / fmaxf(g_pcnt[g], 1.0f);
    float s = 0.f;
    for (int j = lane; j < HID; j += 32)
        s += g_pool[g * HID + j] * inv * Wl[j];
#pragma unroll
    for (int o = 16; o; o >>= 1) s += __shfl_xor_sync(0xFFFFFFFFu, s, o);
    if (lane == 0) out[g] = s + bl[0];
}

// ---------------- launcher: kernel launches ONLY ----------------
extern "C" void kernel_launch(void* const* d_in, const int* in_sizes, int n_in,
                              void* d_out, int out_size) {
    const float* x     = (const float*)d_in[0];
    const int*   ei    = (const int*)d_in[1];
    const int*   em    = (const int*)d_in[2];
    const int*   batch = (const int*)d_in[3];
    const float* W1 = (const float*)d_in[4];
    const float* b1 = (const float*)d_in[5];
    const float* W2 = (const float*)d_in[6];
    const float* b2 = (const float*)d_in[7];
    const float* W3 = (const float*)d_in[8];
    const float* b3 = (const float*)d_in[9];
    const float* Wl = (const float*)d_in[10];
    const float* bl = (const float*)d_in[11];
    float* out = (float*)d_out;

    const int tb  = 256;
    const int gbN = (NN + tb - 1) / tb;
    const int gbE = (NE + tb - 1) / tb;
    const int gbW = (NN * 32 + tb - 1) / tb;

    k_zero   <<<gbN, tb>>>();
    k_prepW  <<<192, 256>>>(W1, W2, W3);
    k_hist   <<<gbE, tb>>>(ei, em);
    // GEMM1 at launch #4 for ncu
    k_gemm_mma<<<GEMM_CTAS, 256>>>(-1, x, 0);
    k_scanA  <<<NBLK, 256>>>();
    k_scanB  <<<1, 256>>>();
    k_scanC  <<<NBLK, 256>>>();
    k_scatter<<<gbE, tb>>>(ei, em);

    // layer 1: g_h[0] -> g_h[1] (relu, all edges)
    k_agg <<<gbW, tb>>>(0, 1, b1, 0, 1, 0, batch);
    // layer 2
    k_gemm_mma<<<GEMM_CTAS, 256>>>(1, x, 1);
    k_agg <<<gbW, tb>>>(1, 2, b2, 1, 1, 0, batch);
    // layer 3 + fused pool
    k_gemm_mma<<<GEMM_CTAS, 256>>>(2, x, 2);
    k_agg <<<gbW, tb>>>(2, 1, b3, 2, 0, 1, batch);

    k_final<<<NG, 32>>>(Wl, bl, out);
}